// round 17
// baseline (speedup 1.0000x reference)
#include <cuda_runtime.h>
#include <cuda_fp16.h>
#include <cstdint>
#include <cstddef>

#define NDIM   4096
#define BT     128
#define KT     64
#define SROW   144            // fp16 tile row bytes (128B data + 16B pad)
#define TILE_B (128 * SROW)   // 18432 B per fp16 tile
// SMEM layout per CTA:
//  [0, 2*TILE_B)            : A16 slots 0,1
//  [2*TILE_B, 4*TILE_B)     : B16 slots 0,1
//  [4*TILE_B, 4*TILE_B+32K) : A32 scratch (single slot, 128 rows x 256B)
#define A16_OFF 0
#define B16_OFF (2 * TILE_B)
#define ASCR_OFF (4 * TILE_B)
#define DSMEM_BYTES (4 * TILE_B + 32768)   // 106496 B -> 2 CTAs/SM

#define NSPLIT 136            // tiles with d >= 16 (split into 2 k-halves)
#define NJOBS  664            // 2*136 + 392 compute jobs
#define NZERO  496            // strictly-upper 128-blocks (zero-fill tail CTAs)

static __device__ __half g_Bh[(size_t)NDIM * NDIM];   // [n][k] fp16 (pre-pass)

// ---------------------------------------------------------------------------
// Pre-pass over 64x64 tiles, grid (64,64,2), 256 thr.
//  z=0: B[k][n] -> Bh[n][k] transpose+convert (k-tiles with kt >= nt&~1)
//  z=1: zero C for the 136 split lower tiles (atomicAdd targets)
// (A conversion now happens inside trimm.)
// ---------------------------------------------------------------------------
__global__ void conv_kernel(const float* __restrict__ B, float* __restrict__ C) {
    __shared__ float t64[64][65];
    const int tid = threadIdx.x;

    if (blockIdx.z == 1) {
        const int rt = blockIdx.y, ct = blockIdx.x;
        const int rb = rt >> 1, cb = ct >> 1;
        if (rb - cb < 16) return;                      // only split tiles
        #pragma unroll
        for (int j = 0; j < 4; j++) {
            const int idx = tid + 256 * j;
            const int r = rt * 64 + (idx >> 4);
            const int c = ct * 64 + (idx & 15) * 4;
            *reinterpret_cast<float4*>(C + (size_t)r * NDIM + c) =
                make_float4(0.f, 0.f, 0.f, 0.f);
        }
        return;
    }

    const int kt = blockIdx.x, nt = blockIdx.y;
    if (kt < (nt & ~1)) return;
    const int bk = kt * 64, bn = nt * 64;
    #pragma unroll
    for (int j = 0; j < 4; j++) {
        const int idx = tid + 256 * j;
        const int kr = idx >> 4, c4 = (idx & 15) * 4;
        const float4 v = *reinterpret_cast<const float4*>(B + (size_t)(bk + kr) * NDIM + bn + c4);
        t64[kr][c4 + 0] = v.x; t64[kr][c4 + 1] = v.y;
        t64[kr][c4 + 2] = v.z; t64[kr][c4 + 3] = v.w;
    }
    __syncthreads();
    #pragma unroll
    for (int j = 0; j < 2; j++) {
        const int idx = tid + 256 * j;
        const int nr = idx >> 3, kc = idx & 7;
        ushort4 o0, o1;
        o0.x = __half_as_ushort(__float2half(t64[kc * 8 + 0][nr]));
        o0.y = __half_as_ushort(__float2half(t64[kc * 8 + 1][nr]));
        o0.z = __half_as_ushort(__float2half(t64[kc * 8 + 2][nr]));
        o0.w = __half_as_ushort(__float2half(t64[kc * 8 + 3][nr]));
        o1.x = __half_as_ushort(__float2half(t64[kc * 8 + 4][nr]));
        o1.y = __half_as_ushort(__float2half(t64[kc * 8 + 5][nr]));
        o1.z = __half_as_ushort(__float2half(t64[kc * 8 + 6][nr]));
        o1.w = __half_as_ushort(__float2half(t64[kc * 8 + 7][nr]));
        ushort4* dst = reinterpret_cast<ushort4*>(g_Bh + (size_t)(bn + nr) * NDIM + bk + kc * 8);
        dst[0] = o0; dst[1] = o1;
    }
}

// ---------------------------------------------------------------------------
__device__ __forceinline__ uint32_t smem_u32(const void* p) {
    uint32_t a;
    asm("{ .reg .u64 t; cvta.to.shared.u64 t, %1; cvt.u32.u64 %0, t; }" : "=r"(a) : "l"(p));
    return a;
}
__device__ __forceinline__ void cpa16(uint32_t dst, const void* src) {
    asm volatile("cp.async.cg.shared.global [%0], [%1], 16;\n" ::"r"(dst), "l"(src));
}

#define LDSM4(r0, r1, r2, r3, addr)                                                    \
    asm volatile("ldmatrix.sync.aligned.m8n8.x4.shared.b16 {%0,%1,%2,%3}, [%4];"       \
                 : "=r"(r0), "=r"(r1), "=r"(r2), "=r"(r3) : "r"(addr))

#define MMA_F16(d, a, b0, b1)                                                          \
    asm volatile(                                                                      \
        "mma.sync.aligned.m16n8k16.row.col.f32.f16.f16.f32 "                           \
        "{%0,%1,%2,%3}, {%4,%5,%6,%7}, {%8,%9}, {%0,%1,%2,%3};\n"                      \
        : "+f"((d)[0]), "+f"((d)[1]), "+f"((d)[2]), "+f"((d)[3])                       \
        : "r"((a)[0]), "r"((a)[1]), "r"((a)[2]), "r"((a)[3]), "r"(b0), "r"(b1))

// ---------------------------------------------------------------------------
// Triangular GEMM with in-kernel A fp32->fp16 conversion.
//  Per chunk (KT=64): cp.async raw A fp32 -> scratch, B fp16 -> B16 slot
//  (distance-1 prefetch); convert scratch -> A16 slot; compute (R12 inner).
//  Jobs: split (d>=16, two k-halves, RED.ADD) / unsplit / zero-fill tail.
// ---------------------------------------------------------------------------
__global__ __launch_bounds__(256, 2) void trimm_kernel(const float* __restrict__ A,
                                                       float* __restrict__ C) {
    extern __shared__ char dsm[];
    const int tid = threadIdx.x;
    const int lane = tid & 31, warp = tid >> 5;

    if (blockIdx.x >= NJOBS) {
        // Zero-fill one strictly-upper 128x128 block.
        int u = blockIdx.x - NJOBS, r = 0;
        #pragma unroll 1
        while (u >= 31 - r) { u -= 31 - r; r++; }
        const int m0 = r * BT, n0 = (r + 1 + u) * BT;
        const float4 z = make_float4(0.f, 0.f, 0.f, 0.f);
        #pragma unroll 1
        for (int i = tid; i < 128 * 32; i += 256)
            reinterpret_cast<float4*>(C + (size_t)(m0 + (i >> 5)) * NDIM + n0)[i & 31] = z;
        return;
    }

    int bm, bn, c0, c1;
    bool use_red = false;
    if (blockIdx.x < 2 * NSPLIT) {
        int p = blockIdx.x >> 1;
        const int h = blockIdx.x & 1;
        int d = 31;
        #pragma unroll 1
        while (p >= 32 - d) { p -= 32 - d; d--; }    // d: 31..16
        bn = p; bm = p + d;
        c0 = h * (d + 1); c1 = c0 + (d + 1);
        use_red = true;
    } else {
        int q = blockIdx.x - 2 * NSPLIT;
        int d = 15;
        #pragma unroll 1
        while (q >= 32 - d) { q -= 32 - d; d--; }    // d: 15..0
        bn = q; bm = q + d;
        c0 = 0; c1 = 2 * (d + 1);
    }

    const int m0 = bm * BT, n0 = bn * BT;
    const uint32_t sb = smem_u32(dsm);

    // cp.async mappings (256 threads):
    //  A32: 32KB/chunk -> 128B/thread: row=tid>>1, h=tid&1, 8x16B at h*128+i*16
    //  B16: 16KB/chunk ->  64B/thread: row=tid>>1, h=tid&1, 4x16B at h*64+i*16
    const int cr = tid >> 1, chf = tid & 1;
    const float*  gA  = A    + (size_t)(m0 + cr) * NDIM + chf * 32;   // fp32
    const __half* gBh = g_Bh + (size_t)(n0 + cr) * NDIM + chf * 32;   // fp16
    const uint32_t ascr_dst = sb + ASCR_OFF + cr * 256 + chf * 128;
    const uint32_t b16_dst  = sb + B16_OFF  + cr * SROW + chf * 64;

    // Warp tile 32m x 64n (R12 mapping: 4x2 warp grid).
    const int wm = (warp >> 1) * 32, wn = (warp & 1) * 64;
    const int mlim = m0 + wm + 31;                // A slice zero if k0s > mlim
    const int nlim = n0 + wn;                     // B slice zero if k0s+16 <= nlim
    uint32_t a_off[2], b_off[4];
    #pragma unroll
    for (int mi = 0; mi < 2; mi++)
        a_off[mi] = (uint32_t)((wm + mi * 16 + (lane & 15)) * SROW + (lane >> 4) * 16);
    #pragma unroll
    for (int p = 0; p < 4; p++) {
        const int quad = lane >> 3;
        b_off[p] = (uint32_t)((wn + p * 16 + (quad >> 1) * 8 + (lane & 7)) * SROW +
                              (quad & 1) * 16);
    }

    float acc[2][8][4];
    #pragma unroll
    for (int mi = 0; mi < 2; mi++)
        #pragma unroll
        for (int ni = 0; ni < 8; ni++)
            #pragma unroll
            for (int r = 0; r < 4; r++) acc[mi][ni][r] = 0.f;

    // Prologue: load chunk c0 (A fp32 -> scratch, B fp16 -> slot c0%2).
    {
        const int k0 = n0 + c0 * KT;
        const uint32_t bd = b16_dst + (c0 & 1) * TILE_B;
        #pragma unroll
        for (int i = 0; i < 8; i++) cpa16(ascr_dst + i * 16, gA + k0 + i * 4);
        #pragma unroll
        for (int i = 0; i < 4; i++) cpa16(bd + i * 16, gBh + k0 + i * 8);
        asm volatile("cp.async.commit_group;\n");
    }

    #pragma unroll 1
    for (int it = c0; it < c1; it++) {
        asm volatile("cp.async.wait_group 0;\n");   // chunk it (A32+B16) resident
        __syncthreads();                            // warps past compute(it-1)

        // Convert A32 scratch -> A16 slot it%2. Thread reads 8 linear float4s.
        {
            const uint32_t a16b = sb + A16_OFF + (it & 1) * TILE_B;
            #pragma unroll
            for (int i = 0; i < 8; i++) {
                const int p = tid + i * 256;          // f4 index 0..2047
                const int row = p >> 4, c16 = p & 15;
                float4 f = *reinterpret_cast<const float4*>(dsm + ASCR_OFF + p * 16);
                __half2 h0 = __floats2half2_rn(f.x, f.y);
                __half2 h1 = __floats2half2_rn(f.z, f.w);
                uint32_t u0 = *reinterpret_cast<uint32_t*>(&h0);
                uint32_t u1 = *reinterpret_cast<uint32_t*>(&h1);
                asm volatile("st.shared.v2.b32 [%0], {%1,%2};\n"
                             :: "r"(a16b + row * SROW + c16 * 8), "r"(u0), "r"(u1)
                             : "memory");
            }
        }
        __syncthreads();                            // conversions visible; scratch free

        // Prefetch chunk it+1 (distance 1: arrival deadline = next iteration).
        if (it + 1 < c1) {
            const int kp = n0 + (it + 1) * KT;
            const uint32_t bd = b16_dst + ((it + 1) & 1) * TILE_B;
            #pragma unroll
            for (int i = 0; i < 8; i++) cpa16(ascr_dst + i * 16, gA + kp + i * 4);
            #pragma unroll
            for (int i = 0; i < 4; i++) cpa16(bd + i * 16, gBh + kp + i * 8);
        }
        asm volatile("cp.async.commit_group;\n");

        // Compute chunk it (identical to R12 inner loop).
        const int k0 = n0 + it * KT;
        const uint32_t sa = sb + A16_OFF + (it & 1) * TILE_B;
        const uint32_t sbB = sb + B16_OFF + (it & 1) * TILE_B;

        bool sk[4];
        #pragma unroll
        for (int kk = 0; kk < 4; kk++)
            sk[kk] = (k0 + 16 * kk > mlim) || (k0 + 16 * kk + 16 <= nlim);

        #pragma unroll
        for (int kk = 0; kk < 4; kk++) {
            if (sk[kk]) continue;
            const uint32_t kb = kk * 32;
            uint32_t ah[2][4], bb[4][4];
            LDSM4(ah[0][0], ah[0][1], ah[0][2], ah[0][3], sa + a_off[0] + kb);
            LDSM4(ah[1][0], ah[1][1], ah[1][2], ah[1][3], sa + a_off[1] + kb);
            #pragma unroll
            for (int p = 0; p < 4; p++)
                LDSM4(bb[p][0], bb[p][1], bb[p][2], bb[p][3], sbB + b_off[p] + kb);
            #pragma unroll
            for (int mi = 0; mi < 2; mi++)
                #pragma unroll
                for (int p = 0; p < 4; p++) {
                    MMA_F16(acc[mi][2 * p],     ah[mi], bb[p][0], bb[p][1]);
                    MMA_F16(acc[mi][2 * p + 1], ah[mi], bb[p][2], bb[p][3]);
                }
        }
    }

    // Epilogue.
    const int g = lane >> 2, tg = lane & 3;
    if (use_red) {
        #pragma unroll
        for (int mi = 0; mi < 2; mi++)
            #pragma unroll
            for (int ni = 0; ni < 8; ni++) {
                const int r0 = m0 + wm + mi * 16 + g;
                const int c0g = n0 + wn + ni * 8 + tg * 2;
                float* p0 = C + (size_t)r0 * NDIM + c0g;
                float* p1 = C + (size_t)(r0 + 8) * NDIM + c0g;
                atomicAdd(p0,     acc[mi][ni][0]);
                atomicAdd(p0 + 1, acc[mi][ni][1]);
                atomicAdd(p1,     acc[mi][ni][2]);
                atomicAdd(p1 + 1, acc[mi][ni][3]);
            }
    } else {
        #pragma unroll
        for (int mi = 0; mi < 2; mi++)
            #pragma unroll
            for (int ni = 0; ni < 8; ni++) {
                const int r0 = m0 + wm + mi * 16 + g;
                const int c0g = n0 + wn + ni * 8 + tg * 2;
                *reinterpret_cast<float2*>(C + (size_t)r0 * NDIM + c0g) =
                    make_float2(acc[mi][ni][0], acc[mi][ni][1]);
                *reinterpret_cast<float2*>(C + (size_t)(r0 + 8) * NDIM + c0g) =
                    make_float2(acc[mi][ni][2], acc[mi][ni][3]);
            }
    }
}

// ---------------------------------------------------------------------------
extern "C" void kernel_launch(void* const* d_in, const int* in_sizes, int n_in,
                              void* d_out, int out_size) {
    (void)in_sizes; (void)n_in; (void)out_size;
    const float* A = (const float*)d_in[0];
    const float* B = (const float*)d_in[1];
    float* C = (float*)d_out;

    static bool attr_done = false;
    if (!attr_done) {
        cudaFuncSetAttribute(trimm_kernel, cudaFuncAttributeMaxDynamicSharedMemorySize,
                             DSMEM_BYTES);
        attr_done = true;
    }

    conv_kernel<<<dim3(64, 64, 2), 256>>>(B, C);
    trimm_kernel<<<NJOBS + NZERO, 256, DSMEM_BYTES>>>(A, C);
}